// round 5
// baseline (speedup 1.0000x reference)
#include <cuda_runtime.h>
#include <cuda_bf16.h>
#include <cstdint>

#define NB 4
#define SQ 1024
#define DM 1280
#define NH 16
#define HD 80
#define MTOT (NB*SQ)      // 4096
#define NQKV (3*DM)       // 3840

// ---------------------------------------------------------------------------
// Scratch (__device__ globals; allocation-free rule)
// ---------------------------------------------------------------------------
__device__ float g_q[NB*NH*SQ*HD];
__device__ float g_k[NB*NH*SQ*HD];

__device__ __nv_bfloat16 xh_g[MTOT*DM],  xl_g[MTOT*DM];
__device__ __nv_bfloat16 wqh_g[NQKV*DM], wql_g[NQKV*DM];
__device__ __nv_bfloat16 wph_g[DM*DM],   wpl_g[DM*DM];
__device__ __nv_bfloat16 qh_g[NB*NH*SQ*HD], ql_g[NB*NH*SQ*HD];
__device__ __nv_bfloat16 kh_g[NB*NH*SQ*HD], kl_g[NB*NH*SQ*HD];
__device__ __nv_bfloat16 vh_g[NB*NH*SQ*HD], vl_g[NB*NH*SQ*HD];
__device__ __nv_bfloat16 ch_g[MTOT*DM],  cl_g[MTOT*DM];

// ---------------------------------------------------------------------------
// helpers
// ---------------------------------------------------------------------------
__device__ __forceinline__ uint32_t s2u(const void* p) {
    uint32_t a;
    asm("{ .reg .u64 t; cvta.to.shared.u64 t, %1; cvt.u32.u64 %0, t; }"
        : "=r"(a) : "l"(p));
    return a;
}
__device__ __forceinline__ void ldm_x4(uint32_t* r, uint32_t addr) {
    asm volatile("ldmatrix.sync.aligned.m8n8.x4.shared.b16 {%0,%1,%2,%3}, [%4];"
        : "=r"(r[0]), "=r"(r[1]), "=r"(r[2]), "=r"(r[3]) : "r"(addr));
}
__device__ __forceinline__ void ldm_x4_t(uint32_t* r, uint32_t addr) {
    asm volatile("ldmatrix.sync.aligned.m8n8.x4.trans.shared.b16 {%0,%1,%2,%3}, [%4];"
        : "=r"(r[0]), "=r"(r[1]), "=r"(r[2]), "=r"(r[3]) : "r"(addr));
}
__device__ __forceinline__ void mma16816(float* c, const uint32_t* a,
                                         uint32_t b0, uint32_t b1) {
    asm volatile(
        "mma.sync.aligned.m16n8k16.row.col.f32.bf16.bf16.f32 "
        "{%0,%1,%2,%3}, {%4,%5,%6,%7}, {%8,%9}, {%0,%1,%2,%3};"
        : "+f"(c[0]), "+f"(c[1]), "+f"(c[2]), "+f"(c[3])
        : "r"(a[0]), "r"(a[1]), "r"(a[2]), "r"(a[3]), "r"(b0), "r"(b1));
}
__device__ __forceinline__ uint32_t packbf(float a, float b) {
    __nv_bfloat162 t = __floats2bfloat162_rn(a, b);
    return *reinterpret_cast<uint32_t*>(&t);
}
__device__ __forceinline__ void cpasync16(uint32_t dst, const void* src) {
    asm volatile("cp.async.ca.shared.global [%0], [%1], 16;"
        :: "r"(dst), "l"(src) : "memory");
}
#define CP_COMMIT() asm volatile("cp.async.commit_group;" ::: "memory")
#define CP_WAIT0()  asm volatile("cp.async.wait_group 0;" ::: "memory")
#define CP_WAIT1()  asm volatile("cp.async.wait_group 1;" ::: "memory")

// ---------------------------------------------------------------------------
// fp32 -> bf16 hi/lo split
// ---------------------------------------------------------------------------
__global__ void __launch_bounds__(256) split_kernel(
    const float* __restrict__ src, __nv_bfloat16* __restrict__ hi,
    __nv_bfloat16* __restrict__ lo, int n4)
{
    const int i = blockIdx.x * 256 + threadIdx.x;
    if (i >= n4) return;
    float4 v = ((const float4*)src)[i];
    __nv_bfloat16 h0 = __float2bfloat16_rn(v.x), h1 = __float2bfloat16_rn(v.y);
    __nv_bfloat16 h2 = __float2bfloat16_rn(v.z), h3 = __float2bfloat16_rn(v.w);
    ((__nv_bfloat162*)hi)[2*i+0] = __nv_bfloat162(h0, h1);
    ((__nv_bfloat162*)hi)[2*i+1] = __nv_bfloat162(h2, h3);
    ((__nv_bfloat162*)lo)[2*i+0] = __floats2bfloat162_rn(
        v.x - __bfloat162float(h0), v.y - __bfloat162float(h1));
    ((__nv_bfloat162*)lo)[2*i+1] = __floats2bfloat162_rn(
        v.z - __bfloat162float(h2), v.w - __bfloat162float(h3));
}

// ===========================================================================
// GEMM: C[m,n] = sum_k A[m,k]*W[n,k] + bias[n], pre-split bf16, mma.sync.
// Tile 128x128, K-stage 32, 3-stage cp.async pipeline, pitch-80 smem.
// Pass-outer MMA ordering: 16 independent accumulator chains per pass.
// ===========================================================================
#define KSTAGE 32
#define NIT (DM / KSTAGE)          // 40
#define PITCH 80
#define MAT_BYTES (128 * PITCH)    // 10240
#define STAGE_BYTES (4 * MAT_BYTES)
#define GEMM_DSMEM (3 * STAGE_BYTES)   // 122880

template<bool QKV>
__global__ void __launch_bounds__(256) gemm_bf16(
    const __nv_bfloat16* __restrict__ Ah_g, const __nv_bfloat16* __restrict__ Al_g,
    const __nv_bfloat16* __restrict__ Bh_g, const __nv_bfloat16* __restrict__ Bl_g,
    const float* __restrict__ bias, float* __restrict__ Cout)
{
    extern __shared__ char dsm_raw[];
    const uint32_t base = s2u(dsm_raw);

    const int tid  = threadIdx.x;
    const int wid  = tid >> 5, lane = tid & 31;
    const int bx = blockIdx.x, by = blockIdx.y;
    const int wm = wid >> 1, wn = wid & 1;      // warp tile: 32(M) x 64(N)

    const __nv_bfloat16* bases[4] = {
        Ah_g + (size_t)(by * 128) * DM, Al_g + (size_t)(by * 128) * DM,
        Bh_g + (size_t)(bx * 128) * DM, Bl_g + (size_t)(bx * 128) * DM };

    auto ISSUE = [&](int it) {
        const uint32_t sb = base + (it % 3) * STAGE_BYTES;
        #pragma unroll
        for (int j = 0; j < 8; j++) {
            const int idx = tid + 256 * j;
            const int mat = idx >> 9;
            const int rem = idx & 511;
            const int r = rem >> 2, c = rem & 3;
            const uint32_t dst = sb + mat * MAT_BYTES + r * PITCH + c * 16;
            const __nv_bfloat16* src = bases[mat] + (size_t)r * DM + it * KSTAGE + c * 8;
            cpasync16(dst, src);
        }
        CP_COMMIT();
    };

    float acc[2][8][4];
    #pragma unroll
    for (int i = 0; i < 2; i++)
        #pragma unroll
        for (int j = 0; j < 8; j++)
            #pragma unroll
            for (int q = 0; q < 4; q++) acc[i][j][q] = 0.f;

    ISSUE(0); ISSUE(1);

    for (int it = 0; it < NIT; ++it) {
        if (it == NIT - 1) { CP_WAIT0(); } else { CP_WAIT1(); }
        __syncthreads();
        if (it + 2 < NIT) ISSUE(it + 2);

        const uint32_t sb = base + (it % 3) * STAGE_BYTES;
        #pragma unroll
        for (int kc = 0; kc < 2; kc++) {
            uint32_t Ah[2][4], Al[2][4];
            #pragma unroll
            for (int mf = 0; mf < 2; mf++) {
                const uint32_t aoff =
                    (uint32_t)((wm*32 + mf*16 + (lane & 15)) * PITCH
                               + kc*32 + (lane >> 4) * 16);
                ldm_x4(Ah[mf], sb + aoff);
                ldm_x4(Al[mf], sb + MAT_BYTES + aoff);
            }
            uint32_t Bh[4][4], Bl[4][4];
            #pragma unroll
            for (int g = 0; g < 4; g++) {
                const int quad = lane >> 3;
                const uint32_t boff =
                    (uint32_t)((wn*64 + g*16 + (quad >> 1) * 8 + (lane & 7)) * PITCH
                               + kc*32 + (quad & 1) * 16);
                ldm_x4(Bh[g], sb + 2*MAT_BYTES + boff);
                ldm_x4(Bl[g], sb + 3*MAT_BYTES + boff);
            }
            // pass-outer: 16 independent chains per pass
            #pragma unroll
            for (int mf = 0; mf < 2; mf++)
                #pragma unroll
                for (int nb = 0; nb < 8; nb++)
                    mma16816(acc[mf][nb], Ah[mf], Bh[nb>>1][(nb&1)*2], Bh[nb>>1][(nb&1)*2+1]);
            #pragma unroll
            for (int mf = 0; mf < 2; mf++)
                #pragma unroll
                for (int nb = 0; nb < 8; nb++)
                    mma16816(acc[mf][nb], Al[mf], Bh[nb>>1][(nb&1)*2], Bh[nb>>1][(nb&1)*2+1]);
            #pragma unroll
            for (int mf = 0; mf < 2; mf++)
                #pragma unroll
                for (int nb = 0; nb < 8; nb++)
                    mma16816(acc[mf][nb], Ah[mf], Bl[nb>>1][(nb&1)*2], Bl[nb>>1][(nb&1)*2+1]);
        }
        __syncthreads();
    }

    // Epilogue
    #pragma unroll
    for (int mf = 0; mf < 2; mf++)
        #pragma unroll
        for (int nb = 0; nb < 8; nb++)
            #pragma unroll
            for (int ci = 0; ci < 2; ci++) {
                const int m = by*128 + wm*32 + mf*16 + (lane >> 2) + ci*8;
                const int n = bx*128 + wn*64 + nb*8 + (lane & 3) * 2;
                float2 v;
                v.x = acc[mf][nb][2*ci+0] + bias[n];
                v.y = acc[mf][nb][2*ci+1] + bias[n+1];
                if (QKV) {
                    const int sel = n / DM;
                    const int r2  = n - sel * DM;
                    const int h   = r2 / HD;
                    const int dd  = r2 - h * HD;
                    const int bb  = m >> 10;
                    const int ss  = m & (SQ - 1);
                    const size_t di = (((size_t)bb * NH + h) * SQ + ss) * HD + dd;
                    if (sel == 0)      *(float2*)&g_q[di] = v;
                    else if (sel == 1) *(float2*)&g_k[di] = v;
                    else {
                        __nv_bfloat16 h0 = __float2bfloat16_rn(v.x);
                        __nv_bfloat16 h1 = __float2bfloat16_rn(v.y);
                        *(__nv_bfloat162*)&vh_g[di] = __nv_bfloat162(h0, h1);
                        *(__nv_bfloat162*)&vl_g[di] = __floats2bfloat162_rn(
                            v.x - __bfloat162float(h0), v.y - __bfloat162float(h1));
                    }
                } else {
                    *(float2*)&Cout[(size_t)m * DM + n] = v;
                }
            }
}

// ---------------------------------------------------------------------------
// RoPE: read g_q/g_k fp32, write rotated bf16 hi/lo
// ---------------------------------------------------------------------------
__global__ void __launch_bounds__(256) rope_kernel(
    const float* __restrict__ cosp, const float* __restrict__ sinp)
{
    const int idx  = blockIdx.x * 256 + threadIdx.x;   // < NB*NH*SQ*40
    const int d    = idx % 40;
    const int rest = idx / 40;
    const int ss   = rest & (SQ - 1);
    const int bh   = rest >> 10;
    const size_t base = ((size_t)bh * SQ + ss) * HD;
    const float c1 = cosp[ss*HD + d],      s1 = sinp[ss*HD + d];
    const float c2 = cosp[ss*HD + d + 40], s2 = sinp[ss*HD + d + 40];

    float q1 = g_q[base + d], q2 = g_q[base + d + 40];
    float o1 = q1*c1 - q2*s1;
    float o2 = q2*c2 + q1*s2;
    __nv_bfloat16 h;
    h = __float2bfloat16_rn(o1); qh_g[base+d]    = h; ql_g[base+d]    = __float2bfloat16_rn(o1 - __bfloat162float(h));
    h = __float2bfloat16_rn(o2); qh_g[base+d+40] = h; ql_g[base+d+40] = __float2bfloat16_rn(o2 - __bfloat162float(h));

    float k1 = g_k[base + d], k2 = g_k[base + d + 40];
    o1 = k1*c1 - k2*s1;
    o2 = k2*c2 + k1*s2;
    h = __float2bfloat16_rn(o1); kh_g[base+d]    = h; kl_g[base+d]    = __float2bfloat16_rn(o1 - __bfloat162float(h));
    h = __float2bfloat16_rn(o2); kh_g[base+d+40] = h; kl_g[base+d+40] = __float2bfloat16_rn(o2 - __bfloat162float(h));
}

// ===========================================================================
// Flash attention on mma.sync. CTA = (qt 64 rows, bh), 4 warps.
// Double-buffered K/V via cp.async; pass-outer MMA ordering; fragment softmax.
// ===========================================================================
#define APITCH 176                       // bytes per 80-elem bf16 row (+pad)
#define AMAT (64*APITCH)                 // 11264 per matrix
#define AQH 0
#define AQL AMAT
#define AKV0 (2*AMAT)                    // stage0 base: KH,KL,VH,VL
#define KV_STAGE (4*AMAT)                // 45056
#define ATTN_SMEM (2*AMAT + 2*KV_STAGE)  // 112640

__global__ void __launch_bounds__(128) attn_tc()
{
    extern __shared__ char dsm_raw[];
    const uint32_t base = s2u(dsm_raw);

    const int tid = threadIdx.x;
    const int w = tid >> 5, lane = tid & 31;
    const int qt = blockIdx.x, bh = blockIdx.y;
    const int b = bh >> 4, h = bh & 15;
    const float scale = 0.11180339887498948f;  // 1/sqrt(80)

    const size_t krow0base = (size_t)bh * SQ;

    auto ISSUE_KV = [&](int kt) {
        const uint32_t sb = base + AKV0 + (kt & 1) * KV_STAGE;
        const size_t krow0 = krow0base + kt * 64;
        const __nv_bfloat16* srcs[4] = { kh_g, kl_g, vh_g, vl_g };
        #pragma unroll
        for (int j = 0; j < 20; j++) {
            const int idx = tid + 128 * j;   // 0..2559
            const int mat = idx / 640;
            const int rem = idx - mat * 640;
            const int r = rem / 10, c = rem - r * 10;
            cpasync16(sb + mat * AMAT + r * APITCH + c * 16,
                      srcs[mat] + (krow0 + r) * HD + c * 8);
        }
        CP_COMMIT();
    };

    // Q tile load (once)
    {
        const size_t qrow0 = krow0base + qt * 64;
        #pragma unroll
        for (int j = 0; j < 10; j++) {
            const int idx = tid + 128 * j;     // 0..1279
            const int mat = idx / 640;
            const int rem = idx - mat * 640;
            const int r = rem / 10, c = rem - r * 10;
            cpasync16(base + (mat ? AQL : AQH) + r * APITCH + c * 16,
                      (mat ? ql_g : qh_g) + (qrow0 + r) * HD + c * 8);
        }
        CP_COMMIT();
    }
    ISSUE_KV(0);

    float oacc[10][4];
    #pragma unroll
    for (int i = 0; i < 10; i++)
        #pragma unroll
        for (int j = 0; j < 4; j++) oacc[i][j] = 0.f;
    float m0 = -1e30f, m1 = -1e30f, l0 = 0.f, l1 = 0.f;

    for (int kt = 0; kt < 16; kt++) {
        if (kt + 1 < 16) { ISSUE_KV(kt + 1); CP_WAIT1(); } else { CP_WAIT0(); }
        __syncthreads();

        const uint32_t kvb = base + AKV0 + (kt & 1) * KV_STAGE;
        const uint32_t sKH = kvb, sKL = kvb + AMAT;
        const uint32_t sVH = kvb + 2*AMAT, sVL = kvb + 3*AMAT;

        // ---- S = Q K^T (64x64), 3-pass split, pass-outer ----
        float sacc[8][4];
        #pragma unroll
        for (int i = 0; i < 8; i++)
            #pragma unroll
            for (int j = 0; j < 4; j++) sacc[i][j] = 0.f;

        #pragma unroll
        for (int kc = 0; kc < 5; kc++) {
            uint32_t Aah[4], Aal[4];
            const uint32_t aoff =
                (uint32_t)((w*16 + (lane & 15)) * APITCH + kc*32 + (lane >> 4) * 16);
            ldm_x4(Aah, base + AQH + aoff);
            ldm_x4(Aal, base + AQL + aoff);
            uint32_t Bh4[4][4], Bl4[4][4];
            #pragma unroll
            for (int g = 0; g < 4; g++) {
                const int quad = lane >> 3;
                const uint32_t boff =
                    (uint32_t)((g*16 + (quad >> 1) * 8 + (lane & 7)) * APITCH
                               + kc*32 + (quad & 1) * 16);
                ldm_x4(Bh4[g], sKH + boff);
                ldm_x4(Bl4[g], sKL + boff);
            }
            #pragma unroll
            for (int g = 0; g < 4; g++)
                #pragma unroll
                for (int hh = 0; hh < 2; hh++)
                    mma16816(sacc[g*2+hh], Aah, Bh4[g][2*hh], Bh4[g][2*hh+1]);
            #pragma unroll
            for (int g = 0; g < 4; g++)
                #pragma unroll
                for (int hh = 0; hh < 2; hh++)
                    mma16816(sacc[g*2+hh], Aal, Bh4[g][2*hh], Bh4[g][2*hh+1]);
            #pragma unroll
            for (int g = 0; g < 4; g++)
                #pragma unroll
                for (int hh = 0; hh < 2; hh++)
                    mma16816(sacc[g*2+hh], Aah, Bl4[g][2*hh], Bl4[g][2*hh+1]);
        }

        // ---- online softmax on fragments ----
        #pragma unroll
        for (int nb = 0; nb < 8; nb++)
            #pragma unroll
            for (int j = 0; j < 4; j++) sacc[nb][j] *= scale;

        float mx0 = -1e30f, mx1 = -1e30f;
        #pragma unroll
        for (int nb = 0; nb < 8; nb++) {
            mx0 = fmaxf(mx0, fmaxf(sacc[nb][0], sacc[nb][1]));
            mx1 = fmaxf(mx1, fmaxf(sacc[nb][2], sacc[nb][3]));
        }
        mx0 = fmaxf(mx0, __shfl_xor_sync(0xffffffffu, mx0, 1));
        mx0 = fmaxf(mx0, __shfl_xor_sync(0xffffffffu, mx0, 2));
        mx1 = fmaxf(mx1, __shfl_xor_sync(0xffffffffu, mx1, 1));
        mx1 = fmaxf(mx1, __shfl_xor_sync(0xffffffffu, mx1, 2));

        const float mn0 = fmaxf(m0, mx0), mn1 = fmaxf(m1, mx1);
        const float al0 = __expf(m0 - mn0), al1 = __expf(m1 - mn1);
        m0 = mn0; m1 = mn1;

        float rs0 = 0.f, rs1 = 0.f;
        #pragma unroll
        for (int nb = 0; nb < 8; nb++) {
            sacc[nb][0] = __expf(sacc[nb][0] - m0);
            sacc[nb][1] = __expf(sacc[nb][1] - m0);
            sacc[nb][2] = __expf(sacc[nb][2] - m1);
            sacc[nb][3] = __expf(sacc[nb][3] - m1);
            rs0 += sacc[nb][0] + sacc[nb][1];
            rs1 += sacc[nb][2] + sacc[nb][3];
        }
        rs0 += __shfl_xor_sync(0xffffffffu, rs0, 1);
        rs0 += __shfl_xor_sync(0xffffffffu, rs0, 2);
        rs1 += __shfl_xor_sync(0xffffffffu, rs1, 1);
        rs1 += __shfl_xor_sync(0xffffffffu, rs1, 2);
        l0 = l0 * al0 + rs0;
        l1 = l1 * al1 + rs1;

        #pragma unroll
        for (int nb = 0; nb < 10; nb++) {
            oacc[nb][0] *= al0; oacc[nb][1] *= al0;
            oacc[nb][2] *= al1; oacc[nb][3] *= al1;
        }

        // ---- O += P @ V, 3-pass, pass-outer per kc ----
        #pragma unroll
        for (int kc = 0; kc < 4; kc++) {
            uint32_t Pa_h[4], Pa_l[4];
            #pragma unroll
            for (int half2i = 0; half2i < 2; half2i++) {
                const int nb = 2*kc + half2i;
                float f0 = sacc[nb][0], f1 = sacc[nb][1];
                float f2 = sacc[nb][2], f3 = sacc[nb][3];
                float h0 = __bfloat162float(__float2bfloat16_rn(f0));
                float h1 = __bfloat162float(__float2bfloat16_rn(f1));
                float h2 = __bfloat162float(__float2bfloat16_rn(f2));
                float h3 = __bfloat162float(__float2bfloat16_rn(f3));
                Pa_h[2*half2i+0] = packbf(h0, h1);
                Pa_h[2*half2i+1] = packbf(h2, h3);
                Pa_l[2*half2i+0] = packbf(f0 - h0, f1 - h1);
                Pa_l[2*half2i+1] = packbf(f2 - h2, f3 - h3);
            }
            uint32_t Vh4[5][4], Vl4[5][4];
            #pragma unroll
            for (int vg = 0; vg < 5; vg++) {
                const int vrow = kc*16 + ((lane >> 3) & 1) * 8 + (lane & 7);
                const int vcol = vg*16 + (lane >> 4) * 8;
                const uint32_t voff = (uint32_t)(vrow * APITCH + vcol * 2);
                ldm_x4_t(Vh4[vg], sVH + voff);
                ldm_x4_t(Vl4[vg], sVL + voff);
            }
            #pragma unroll
            for (int vg = 0; vg < 5; vg++)
                #pragma unroll
                for (int hh = 0; hh < 2; hh++)
                    mma16816(oacc[vg*2+hh], Pa_h, Vh4[vg][2*hh], Vh4[vg][2*hh+1]);
            #pragma unroll
            for (int vg = 0; vg < 5; vg++)
                #pragma unroll
                for (int hh = 0; hh < 2; hh++)
                    mma16816(oacc[vg*2+hh], Pa_l, Vh4[vg][2*hh], Vh4[vg][2*hh+1]);
            #pragma unroll
            for (int vg = 0; vg < 5; vg++)
                #pragma unroll
                for (int hh = 0; hh < 2; hh++)
                    mma16816(oacc[vg*2+hh], Pa_h, Vl4[vg][2*hh], Vl4[vg][2*hh+1]);
        }
        __syncthreads();
    }

    // ---- finalize: normalize and write ch/cl ----
    const float inv0 = 1.f / l0, inv1 = 1.f / l1;
    const int s0 = qt*64 + w*16 + (lane >> 2);
    const int s1 = s0 + 8;
    #pragma unroll
    for (int nb = 0; nb < 10; nb++) {
        const int d = nb*8 + (lane & 3) * 2;
        {
            const size_t di = ((size_t)b * SQ + s0) * DM + h * HD + d;
            float o0 = oacc[nb][0] * inv0, o1 = oacc[nb][1] * inv0;
            __nv_bfloat16 h0 = __float2bfloat16_rn(o0);
            __nv_bfloat16 h1 = __float2bfloat16_rn(o1);
            *(__nv_bfloat162*)&ch_g[di] = __nv_bfloat162(h0, h1);
            *(__nv_bfloat162*)&cl_g[di] = __floats2bfloat162_rn(
                o0 - __bfloat162float(h0), o1 - __bfloat162float(h1));
        }
        {
            const size_t di = ((size_t)b * SQ + s1) * DM + h * HD + d;
            float o0 = oacc[nb][2] * inv1, o1 = oacc[nb][3] * inv1;
            __nv_bfloat16 h0 = __float2bfloat16_rn(o0);
            __nv_bfloat16 h1 = __float2bfloat16_rn(o1);
            *(__nv_bfloat162*)&ch_g[di] = __nv_bfloat162(h0, h1);
            *(__nv_bfloat162*)&cl_g[di] = __floats2bfloat162_rn(
                o0 - __bfloat162float(h0), o1 - __bfloat162float(h1));
        }
    }
}

// ---------------------------------------------------------------------------
extern "C" void kernel_launch(void* const* d_in, const int* in_sizes, int n_in,
                              void* d_out, int out_size)
{
    (void)in_sizes; (void)n_in; (void)out_size;
    const float* x     = (const float*)d_in[0];
    const float* cosp  = (const float*)d_in[1];
    const float* sinp  = (const float*)d_in[2];
    const float* Wqkv  = (const float*)d_in[3];
    const float* bqkv  = (const float*)d_in[4];
    const float* Wproj = (const float*)d_in[5];
    const float* bproj = (const float*)d_in[6];
    float* out = (float*)d_out;

    cudaFuncSetAttribute(gemm_bf16<true>,
                         cudaFuncAttributeMaxDynamicSharedMemorySize, GEMM_DSMEM);
    cudaFuncSetAttribute(gemm_bf16<false>,
                         cudaFuncAttributeMaxDynamicSharedMemorySize, GEMM_DSMEM);
    cudaFuncSetAttribute(attn_tc,
                         cudaFuncAttributeMaxDynamicSharedMemorySize, ATTN_SMEM);

    __nv_bfloat16 *xh, *xl, *wqh, *wql, *wph, *wpl, *ch, *cl;
    cudaGetSymbolAddress((void**)&xh,  xh_g);
    cudaGetSymbolAddress((void**)&xl,  xl_g);
    cudaGetSymbolAddress((void**)&wqh, wqh_g);
    cudaGetSymbolAddress((void**)&wql, wql_g);
    cudaGetSymbolAddress((void**)&wph, wph_g);
    cudaGetSymbolAddress((void**)&wpl, wpl_g);
    cudaGetSymbolAddress((void**)&ch,  ch_g);
    cudaGetSymbolAddress((void**)&cl,  cl_g);

    // 0) splits
    split_kernel<<<(MTOT*DM/4 + 255)/256, 256>>>(x, xh, xl, MTOT*DM/4);
    split_kernel<<<(NQKV*DM/4 + 255)/256, 256>>>(Wqkv, wqh, wql, NQKV*DM/4);
    split_kernel<<<(DM*DM/4 + 255)/256, 256>>>(Wproj, wph, wpl, DM*DM/4);
    // 1) QKV GEMM: q,k fp32 head-major + v bf16 hi/lo
    gemm_bf16<true><<<dim3(NQKV/128, MTOT/128), 256, GEMM_DSMEM>>>(
        xh, xl, wqh, wql, bqkv, nullptr);
    // 2) RoPE -> qh/ql, kh/kl
    rope_kernel<<<(NB*NH*SQ*40)/256, 256>>>(cosp, sinp);
    // 3) attention -> ch/cl
    attn_tc<<<dim3(SQ/64, NB*NH), 128, ATTN_SMEM>>>();
    // 4) output projection
    gemm_bf16<false><<<dim3(DM/128, MTOT/128), 256, GEMM_DSMEM>>>(
        ch, cl, wph, wpl, bproj, out);
}

// round 6
// speedup vs baseline: 1.0819x; 1.0819x over previous
#include <cuda_runtime.h>
#include <cuda_bf16.h>
#include <cstdint>

#define NB 4
#define SQ 1024
#define DM 1280
#define NH 16
#define HD 80
#define MTOT (NB*SQ)      // 4096
#define NQKV (3*DM)       // 3840

// ---------------------------------------------------------------------------
// Scratch (__device__ globals; allocation-free rule)
// ---------------------------------------------------------------------------
__device__ float g_q[NB*NH*SQ*HD];
__device__ float g_k[NB*NH*SQ*HD];

__device__ __nv_bfloat16 xh_g[MTOT*DM],  xl_g[MTOT*DM];
__device__ __nv_bfloat16 wqh_g[NQKV*DM], wql_g[NQKV*DM];
__device__ __nv_bfloat16 wph_g[DM*DM],   wpl_g[DM*DM];
__device__ __nv_bfloat16 qh_g[NB*NH*SQ*HD], ql_g[NB*NH*SQ*HD];
__device__ __nv_bfloat16 kh_g[NB*NH*SQ*HD], kl_g[NB*NH*SQ*HD];
__device__ __nv_bfloat16 vh_g[NB*NH*SQ*HD], vl_g[NB*NH*SQ*HD];
__device__ __nv_bfloat16 ch_g[MTOT*DM],  cl_g[MTOT*DM];

// ---------------------------------------------------------------------------
// helpers
// ---------------------------------------------------------------------------
__device__ __forceinline__ uint32_t s2u(const void* p) {
    uint32_t a;
    asm("{ .reg .u64 t; cvta.to.shared.u64 t, %1; cvt.u32.u64 %0, t; }"
        : "=r"(a) : "l"(p));
    return a;
}
__device__ __forceinline__ void ldm_x4(uint32_t* r, uint32_t addr) {
    asm volatile("ldmatrix.sync.aligned.m8n8.x4.shared.b16 {%0,%1,%2,%3}, [%4];"
        : "=r"(r[0]), "=r"(r[1]), "=r"(r[2]), "=r"(r[3]) : "r"(addr));
}
__device__ __forceinline__ void ldm_x4_t(uint32_t* r, uint32_t addr) {
    asm volatile("ldmatrix.sync.aligned.m8n8.x4.trans.shared.b16 {%0,%1,%2,%3}, [%4];"
        : "=r"(r[0]), "=r"(r[1]), "=r"(r[2]), "=r"(r[3]) : "r"(addr));
}
__device__ __forceinline__ void mma16816(float* c, const uint32_t* a,
                                         uint32_t b0, uint32_t b1) {
    asm volatile(
        "mma.sync.aligned.m16n8k16.row.col.f32.bf16.bf16.f32 "
        "{%0,%1,%2,%3}, {%4,%5,%6,%7}, {%8,%9}, {%0,%1,%2,%3};"
        : "+f"(c[0]), "+f"(c[1]), "+f"(c[2]), "+f"(c[3])
        : "r"(a[0]), "r"(a[1]), "r"(a[2]), "r"(a[3]), "r"(b0), "r"(b1));
}
__device__ __forceinline__ uint32_t packbf(float a, float b) {
    __nv_bfloat162 t = __floats2bfloat162_rn(a, b);
    return *reinterpret_cast<uint32_t*>(&t);
}
__device__ __forceinline__ void cpasync16(uint32_t dst, const void* src) {
    asm volatile("cp.async.ca.shared.global [%0], [%1], 16;"
        :: "r"(dst), "l"(src) : "memory");
}
#define CP_COMMIT() asm volatile("cp.async.commit_group;" ::: "memory")
#define CP_WAIT0()  asm volatile("cp.async.wait_group 0;" ::: "memory")
#define CP_WAIT1()  asm volatile("cp.async.wait_group 1;" ::: "memory")

// ---------------------------------------------------------------------------
// fp32 -> bf16 hi/lo split
// ---------------------------------------------------------------------------
__global__ void __launch_bounds__(256) split_kernel(
    const float* __restrict__ src, __nv_bfloat16* __restrict__ hi,
    __nv_bfloat16* __restrict__ lo, int n4)
{
    const int i = blockIdx.x * 256 + threadIdx.x;
    if (i >= n4) return;
    float4 v = ((const float4*)src)[i];
    __nv_bfloat16 h0 = __float2bfloat16_rn(v.x), h1 = __float2bfloat16_rn(v.y);
    __nv_bfloat16 h2 = __float2bfloat16_rn(v.z), h3 = __float2bfloat16_rn(v.w);
    ((__nv_bfloat162*)hi)[2*i+0] = __nv_bfloat162(h0, h1);
    ((__nv_bfloat162*)hi)[2*i+1] = __nv_bfloat162(h2, h3);
    ((__nv_bfloat162*)lo)[2*i+0] = __floats2bfloat162_rn(
        v.x - __bfloat162float(h0), v.y - __bfloat162float(h1));
    ((__nv_bfloat162*)lo)[2*i+1] = __floats2bfloat162_rn(
        v.z - __bfloat162float(h2), v.w - __bfloat162float(h3));
}

// ===========================================================================
// GEMM: C[m,n] = sum_k A[m,k]*W[n,k] + bias[n], pre-split bf16, mma.sync.
// Tile 128x128, K-stage 32, TWO-stage cp.async pipeline (80KB smem),
// 2 CTAs/SM for cross-CTA latency hiding.
// ===========================================================================
#define KSTAGE 32
#define NIT (DM / KSTAGE)          // 40
#define PITCH 80
#define MAT_BYTES (128 * PITCH)    // 10240
#define STAGE_BYTES (4 * MAT_BYTES)
#define GEMM_DSMEM (2 * STAGE_BYTES)   // 81920

template<bool QKV>
__global__ void __launch_bounds__(256, 2) gemm_bf16(
    const __nv_bfloat16* __restrict__ Ah_g, const __nv_bfloat16* __restrict__ Al_g,
    const __nv_bfloat16* __restrict__ Bh_g, const __nv_bfloat16* __restrict__ Bl_g,
    const float* __restrict__ bias, float* __restrict__ Cout)
{
    extern __shared__ char dsm_raw[];
    const uint32_t base = s2u(dsm_raw);

    const int tid  = threadIdx.x;
    const int wid  = tid >> 5, lane = tid & 31;
    const int bx = blockIdx.x, by = blockIdx.y;
    const int wm = wid >> 1, wn = wid & 1;      // warp tile: 32(M) x 64(N)

    const __nv_bfloat16* bases[4] = {
        Ah_g + (size_t)(by * 128) * DM, Al_g + (size_t)(by * 128) * DM,
        Bh_g + (size_t)(bx * 128) * DM, Bl_g + (size_t)(bx * 128) * DM };

    auto ISSUE = [&](int it) {
        const uint32_t sb = base + (it & 1) * STAGE_BYTES;
        #pragma unroll
        for (int j = 0; j < 8; j++) {
            const int idx = tid + 256 * j;
            const int mat = idx >> 9;
            const int rem = idx & 511;
            const int r = rem >> 2, c = rem & 3;
            const uint32_t dst = sb + mat * MAT_BYTES + r * PITCH + c * 16;
            const __nv_bfloat16* src = bases[mat] + (size_t)r * DM + it * KSTAGE + c * 8;
            cpasync16(dst, src);
        }
        CP_COMMIT();
    };

    float acc[2][8][4];
    #pragma unroll
    for (int i = 0; i < 2; i++)
        #pragma unroll
        for (int j = 0; j < 8; j++)
            #pragma unroll
            for (int q = 0; q < 4; q++) acc[i][j][q] = 0.f;

    ISSUE(0); ISSUE(1);

    for (int it = 0; it < NIT; ++it) {
        if (it == NIT - 1) { CP_WAIT0(); } else { CP_WAIT1(); }
        __syncthreads();

        const uint32_t sb = base + (it & 1) * STAGE_BYTES;
        #pragma unroll
        for (int kc = 0; kc < 2; kc++) {
            uint32_t Ah[2][4], Al[2][4];
            #pragma unroll
            for (int mf = 0; mf < 2; mf++) {
                const uint32_t aoff =
                    (uint32_t)((wm*32 + mf*16 + (lane & 15)) * PITCH
                               + kc*32 + (lane >> 4) * 16);
                ldm_x4(Ah[mf], sb + aoff);
                ldm_x4(Al[mf], sb + MAT_BYTES + aoff);
            }
            uint32_t Bh[4][4], Bl[4][4];
            #pragma unroll
            for (int g = 0; g < 4; g++) {
                const int quad = lane >> 3;
                const uint32_t boff =
                    (uint32_t)((wn*64 + g*16 + (quad >> 1) * 8 + (lane & 7)) * PITCH
                               + kc*32 + (quad & 1) * 16);
                ldm_x4(Bh[g], sb + 2*MAT_BYTES + boff);
                ldm_x4(Bl[g], sb + 3*MAT_BYTES + boff);
            }
            #pragma unroll
            for (int mf = 0; mf < 2; mf++)
                #pragma unroll
                for (int nb = 0; nb < 8; nb++)
                    mma16816(acc[mf][nb], Ah[mf], Bh[nb>>1][(nb&1)*2], Bh[nb>>1][(nb&1)*2+1]);
            #pragma unroll
            for (int mf = 0; mf < 2; mf++)
                #pragma unroll
                for (int nb = 0; nb < 8; nb++)
                    mma16816(acc[mf][nb], Al[mf], Bh[nb>>1][(nb&1)*2], Bh[nb>>1][(nb&1)*2+1]);
            #pragma unroll
            for (int mf = 0; mf < 2; mf++)
                #pragma unroll
                for (int nb = 0; nb < 8; nb++)
                    mma16816(acc[mf][nb], Ah[mf], Bl[nb>>1][(nb&1)*2], Bl[nb>>1][(nb&1)*2+1]);
        }
        __syncthreads();
        if (it + 2 < NIT) ISSUE(it + 2);
    }

    // Epilogue
    #pragma unroll
    for (int mf = 0; mf < 2; mf++)
        #pragma unroll
        for (int nb = 0; nb < 8; nb++)
            #pragma unroll
            for (int ci = 0; ci < 2; ci++) {
                const int m = by*128 + wm*32 + mf*16 + (lane >> 2) + ci*8;
                const int n = bx*128 + wn*64 + nb*8 + (lane & 3) * 2;
                float2 v;
                v.x = acc[mf][nb][2*ci+0] + bias[n];
                v.y = acc[mf][nb][2*ci+1] + bias[n+1];
                if (QKV) {
                    const int sel = n / DM;
                    const int r2  = n - sel * DM;
                    const int h   = r2 / HD;
                    const int dd  = r2 - h * HD;
                    const int bb  = m >> 10;
                    const int ss  = m & (SQ - 1);
                    const size_t di = (((size_t)bb * NH + h) * SQ + ss) * HD + dd;
                    if (sel == 0)      *(float2*)&g_q[di] = v;
                    else if (sel == 1) *(float2*)&g_k[di] = v;
                    else {
                        __nv_bfloat16 h0 = __float2bfloat16_rn(v.x);
                        __nv_bfloat16 h1 = __float2bfloat16_rn(v.y);
                        *(__nv_bfloat162*)&vh_g[di] = __nv_bfloat162(h0, h1);
                        *(__nv_bfloat162*)&vl_g[di] = __floats2bfloat162_rn(
                            v.x - __bfloat162float(h0), v.y - __bfloat162float(h1));
                    }
                } else {
                    *(float2*)&Cout[(size_t)m * DM + n] = v;
                }
            }
}

// ---------------------------------------------------------------------------
// RoPE: read g_q/g_k fp32, write rotated bf16 hi/lo
// ---------------------------------------------------------------------------
__global__ void __launch_bounds__(256) rope_kernel(
    const float* __restrict__ cosp, const float* __restrict__ sinp)
{
    const int idx  = blockIdx.x * 256 + threadIdx.x;   // < NB*NH*SQ*40
    const int d    = idx % 40;
    const int rest = idx / 40;
    const int ss   = rest & (SQ - 1);
    const int bh   = rest >> 10;
    const size_t base = ((size_t)bh * SQ + ss) * HD;
    const float c1 = cosp[ss*HD + d],      s1 = sinp[ss*HD + d];
    const float c2 = cosp[ss*HD + d + 40], s2 = sinp[ss*HD + d + 40];

    float q1 = g_q[base + d], q2 = g_q[base + d + 40];
    float o1 = q1*c1 - q2*s1;
    float o2 = q2*c2 + q1*s2;
    __nv_bfloat16 h;
    h = __float2bfloat16_rn(o1); qh_g[base+d]    = h; ql_g[base+d]    = __float2bfloat16_rn(o1 - __bfloat162float(h));
    h = __float2bfloat16_rn(o2); qh_g[base+d+40] = h; ql_g[base+d+40] = __float2bfloat16_rn(o2 - __bfloat162float(h));

    float k1 = g_k[base + d], k2 = g_k[base + d + 40];
    o1 = k1*c1 - k2*s1;
    o2 = k2*c2 + k1*s2;
    h = __float2bfloat16_rn(o1); kh_g[base+d]    = h; kl_g[base+d]    = __float2bfloat16_rn(o1 - __bfloat162float(h));
    h = __float2bfloat16_rn(o2); kh_g[base+d+40] = h; kl_g[base+d+40] = __float2bfloat16_rn(o2 - __bfloat162float(h));
}

// ===========================================================================
// Flash attention on mma.sync. CTA = (q-tile 128 rows, bh), 8 warps (256 thr).
// Double-buffered K/V via cp.async; fragment softmax; bf16 hi/lo output.
// ===========================================================================
#define APITCH 176                        // bytes per 80-elem bf16 row (+pad)
#define AMATQ (128*APITCH)                // 22528 per Q matrix (128 rows)
#define AMAT64 (64*APITCH)                // 11264 per KV matrix (64 rows)
#define AQH 0
#define AQL AMATQ
#define AKV0 (2*AMATQ)                    // 45056
#define KV_STAGE (4*AMAT64)               // 45056
#define ATTN_SMEM (2*AMATQ + 2*KV_STAGE)  // 135168

__global__ void __launch_bounds__(256) attn_tc()
{
    extern __shared__ char dsm_raw[];
    const uint32_t base = s2u(dsm_raw);

    const int tid = threadIdx.x;
    const int w = tid >> 5, lane = tid & 31;
    const int qt = blockIdx.x, bh = blockIdx.y;
    const int b = bh >> 4, h = bh & 15;
    const float scale = 0.11180339887498948f;  // 1/sqrt(80)

    const size_t krow0base = (size_t)bh * SQ;

    auto ISSUE_KV = [&](int kt) {
        const uint32_t sb = base + AKV0 + (kt & 1) * KV_STAGE;
        const size_t krow0 = krow0base + kt * 64;
        const __nv_bfloat16* srcs[4] = { kh_g, kl_g, vh_g, vl_g };
        #pragma unroll
        for (int j = 0; j < 10; j++) {
            const int idx = tid + 256 * j;   // 0..2559
            const int mat = idx / 640;
            const int rem = idx - mat * 640;
            const int r = rem / 10, c = rem - r * 10;
            cpasync16(sb + mat * AMAT64 + r * APITCH + c * 16,
                      srcs[mat] + (krow0 + r) * HD + c * 8);
        }
        CP_COMMIT();
    };

    // Q tile load (once): 128 rows x 10 chunks x 2 matrices = 2560
    {
        const size_t qrow0 = krow0base + qt * 128;
        #pragma unroll
        for (int j = 0; j < 10; j++) {
            const int idx = tid + 256 * j;
            const int mat = idx / 1280;
            const int rem = idx - mat * 1280;
            const int r = rem / 10, c = rem - r * 10;
            cpasync16(base + (mat ? AQL : AQH) + r * APITCH + c * 16,
                      (mat ? ql_g : qh_g) + (qrow0 + r) * HD + c * 8);
        }
        CP_COMMIT();
    }
    ISSUE_KV(0);

    float oacc[10][4];
    #pragma unroll
    for (int i = 0; i < 10; i++)
        #pragma unroll
        for (int j = 0; j < 4; j++) oacc[i][j] = 0.f;
    float m0 = -1e30f, m1 = -1e30f, l0 = 0.f, l1 = 0.f;

    for (int kt = 0; kt < 16; kt++) {
        if (kt + 1 < 16) { ISSUE_KV(kt + 1); CP_WAIT1(); } else { CP_WAIT0(); }
        __syncthreads();

        const uint32_t kvb = base + AKV0 + (kt & 1) * KV_STAGE;
        const uint32_t sKH = kvb, sKL = kvb + AMAT64;
        const uint32_t sVH = kvb + 2*AMAT64, sVL = kvb + 3*AMAT64;

        // ---- S = Q K^T (16x64 per warp), 3-pass split ----
        float sacc[8][4];
        #pragma unroll
        for (int i = 0; i < 8; i++)
            #pragma unroll
            for (int j = 0; j < 4; j++) sacc[i][j] = 0.f;

        #pragma unroll
        for (int kc = 0; kc < 5; kc++) {
            uint32_t Aah[4], Aal[4];
            const uint32_t aoff =
                (uint32_t)((w*16 + (lane & 15)) * APITCH + kc*32 + (lane >> 4) * 16);
            ldm_x4(Aah, base + AQH + aoff);
            ldm_x4(Aal, base + AQL + aoff);
            uint32_t Bh4[4][4], Bl4[4][4];
            #pragma unroll
            for (int g = 0; g < 4; g++) {
                const int quad = lane >> 3;
                const uint32_t boff =
                    (uint32_t)((g*16 + (quad >> 1) * 8 + (lane & 7)) * APITCH
                               + kc*32 + (quad & 1) * 16);
                ldm_x4(Bh4[g], sKH + boff);
                ldm_x4(Bl4[g], sKL + boff);
            }
            #pragma unroll
            for (int g = 0; g < 4; g++)
                #pragma unroll
                for (int hh = 0; hh < 2; hh++)
                    mma16816(sacc[g*2+hh], Aah, Bh4[g][2*hh], Bh4[g][2*hh+1]);
            #pragma unroll
            for (int g = 0; g < 4; g++)
                #pragma unroll
                for (int hh = 0; hh < 2; hh++)
                    mma16816(sacc[g*2+hh], Aal, Bh4[g][2*hh], Bh4[g][2*hh+1]);
            #pragma unroll
            for (int g = 0; g < 4; g++)
                #pragma unroll
                for (int hh = 0; hh < 2; hh++)
                    mma16816(sacc[g*2+hh], Aah, Bl4[g][2*hh], Bl4[g][2*hh+1]);
        }

        // ---- online softmax on fragments ----
        #pragma unroll
        for (int nb = 0; nb < 8; nb++)
            #pragma unroll
            for (int j = 0; j < 4; j++) sacc[nb][j] *= scale;

        float mx0 = -1e30f, mx1 = -1e30f;
        #pragma unroll
        for (int nb = 0; nb < 8; nb++) {
            mx0 = fmaxf(mx0, fmaxf(sacc[nb][0], sacc[nb][1]));
            mx1 = fmaxf(mx1, fmaxf(sacc[nb][2], sacc[nb][3]));
        }
        mx0 = fmaxf(mx0, __shfl_xor_sync(0xffffffffu, mx0, 1));
        mx0 = fmaxf(mx0, __shfl_xor_sync(0xffffffffu, mx0, 2));
        mx1 = fmaxf(mx1, __shfl_xor_sync(0xffffffffu, mx1, 1));
        mx1 = fmaxf(mx1, __shfl_xor_sync(0xffffffffu, mx1, 2));

        const float mn0 = fmaxf(m0, mx0), mn1 = fmaxf(m1, mx1);
        const float al0 = __expf(m0 - mn0), al1 = __expf(m1 - mn1);
        m0 = mn0; m1 = mn1;

        float rs0 = 0.f, rs1 = 0.f;
        #pragma unroll
        for (int nb = 0; nb < 8; nb++) {
            sacc[nb][0] = __expf(sacc[nb][0] - m0);
            sacc[nb][1] = __expf(sacc[nb][1] - m0);
            sacc[nb][2] = __expf(sacc[nb][2] - m1);
            sacc[nb][3] = __expf(sacc[nb][3] - m1);
            rs0 += sacc[nb][0] + sacc[nb][1];
            rs1 += sacc[nb][2] + sacc[nb][3];
        }
        rs0 += __shfl_xor_sync(0xffffffffu, rs0, 1);
        rs0 += __shfl_xor_sync(0xffffffffu, rs0, 2);
        rs1 += __shfl_xor_sync(0xffffffffu, rs1, 1);
        rs1 += __shfl_xor_sync(0xffffffffu, rs1, 2);
        l0 = l0 * al0 + rs0;
        l1 = l1 * al1 + rs1;

        #pragma unroll
        for (int nb = 0; nb < 10; nb++) {
            oacc[nb][0] *= al0; oacc[nb][1] *= al0;
            oacc[nb][2] *= al1; oacc[nb][3] *= al1;
        }

        // ---- O += P @ V, 3-pass ----
        #pragma unroll
        for (int kc = 0; kc < 4; kc++) {
            uint32_t Pa_h[4], Pa_l[4];
            #pragma unroll
            for (int half2i = 0; half2i < 2; half2i++) {
                const int nb = 2*kc + half2i;
                float f0 = sacc[nb][0], f1 = sacc[nb][1];
                float f2 = sacc[nb][2], f3 = sacc[nb][3];
                float h0 = __bfloat162float(__float2bfloat16_rn(f0));
                float h1 = __bfloat162float(__float2bfloat16_rn(f1));
                float h2 = __bfloat162float(__float2bfloat16_rn(f2));
                float h3 = __bfloat162float(__float2bfloat16_rn(f3));
                Pa_h[2*half2i+0] = packbf(h0, h1);
                Pa_h[2*half2i+1] = packbf(h2, h3);
                Pa_l[2*half2i+0] = packbf(f0 - h0, f1 - h1);
                Pa_l[2*half2i+1] = packbf(f2 - h2, f3 - h3);
            }
            uint32_t Vh4[5][4], Vl4[5][4];
            #pragma unroll
            for (int vg = 0; vg < 5; vg++) {
                const int vrow = kc*16 + ((lane >> 3) & 1) * 8 + (lane & 7);
                const int vcol = vg*16 + (lane >> 4) * 8;
                const uint32_t voff = (uint32_t)(vrow * APITCH + vcol * 2);
                ldm_x4_t(Vh4[vg], sVH + voff);
                ldm_x4_t(Vl4[vg], sVL + voff);
            }
            #pragma unroll
            for (int vg = 0; vg < 5; vg++)
                #pragma unroll
                for (int hh = 0; hh < 2; hh++)
                    mma16816(oacc[vg*2+hh], Pa_h, Vh4[vg][2*hh], Vh4[vg][2*hh+1]);
            #pragma unroll
            for (int vg = 0; vg < 5; vg++)
                #pragma unroll
                for (int hh = 0; hh < 2; hh++)
                    mma16816(oacc[vg*2+hh], Pa_l, Vh4[vg][2*hh], Vh4[vg][2*hh+1]);
            #pragma unroll
            for (int vg = 0; vg < 5; vg++)
                #pragma unroll
                for (int hh = 0; hh < 2; hh++)
                    mma16816(oacc[vg*2+hh], Pa_h, Vl4[vg][2*hh], Vl4[vg][2*hh+1]);
        }
        __syncthreads();
    }

    // ---- finalize: normalize and write ch/cl ----
    const float inv0 = 1.f / l0, inv1 = 1.f / l1;
    const int s0 = qt*128 + w*16 + (lane >> 2);
    const int s1 = s0 + 8;
    #pragma unroll
    for (int nb = 0; nb < 10; nb++) {
        const int d = nb*8 + (lane & 3) * 2;
        {
            const size_t di = ((size_t)b * SQ + s0) * DM + h * HD + d;
            float o0 = oacc[nb][0] * inv0, o1 = oacc[nb][1] * inv0;
            __nv_bfloat16 h0 = __float2bfloat16_rn(o0);
            __nv_bfloat16 h1 = __float2bfloat16_rn(o1);
            *(__nv_bfloat162*)&ch_g[di] = __nv_bfloat162(h0, h1);
            *(__nv_bfloat162*)&cl_g[di] = __floats2bfloat162_rn(
                o0 - __bfloat162float(h0), o1 - __bfloat162float(h1));
        }
        {
            const size_t di = ((size_t)b * SQ + s1) * DM + h * HD + d;
            float o0 = oacc[nb][2] * inv1, o1 = oacc[nb][3] * inv1;
            __nv_bfloat16 h0 = __float2bfloat16_rn(o0);
            __nv_bfloat16 h1 = __float2bfloat16_rn(o1);
            *(__nv_bfloat162*)&ch_g[di] = __nv_bfloat162(h0, h1);
            *(__nv_bfloat162*)&cl_g[di] = __floats2bfloat162_rn(
                o0 - __bfloat162float(h0), o1 - __bfloat162float(h1));
        }
    }
}

// ---------------------------------------------------------------------------
extern "C" void kernel_launch(void* const* d_in, const int* in_sizes, int n_in,
                              void* d_out, int out_size)
{
    (void)in_sizes; (void)n_in; (void)out_size;
    const float* x     = (const float*)d_in[0];
    const float* cosp  = (const float*)d_in[1];
    const float* sinp  = (const float*)d_in[2];
    const float* Wqkv  = (const float*)d_in[3];
    const float* bqkv  = (const float*)d_in[4];
    const float* Wproj = (const float*)d_in[5];
    const float* bproj = (const float*)d_in[6];
    float* out = (float*)d_out;

    cudaFuncSetAttribute(gemm_bf16<true>,
                         cudaFuncAttributeMaxDynamicSharedMemorySize, GEMM_DSMEM);
    cudaFuncSetAttribute(gemm_bf16<false>,
                         cudaFuncAttributeMaxDynamicSharedMemorySize, GEMM_DSMEM);
    cudaFuncSetAttribute(attn_tc,
                         cudaFuncAttributeMaxDynamicSharedMemorySize, ATTN_SMEM);

    __nv_bfloat16 *xh, *xl, *wqh, *wql, *wph, *wpl, *ch, *cl;
    cudaGetSymbolAddress((void**)&xh,  xh_g);
    cudaGetSymbolAddress((void**)&xl,  xl_g);
    cudaGetSymbolAddress((void**)&wqh, wqh_g);
    cudaGetSymbolAddress((void**)&wql, wql_g);
    cudaGetSymbolAddress((void**)&wph, wph_g);
    cudaGetSymbolAddress((void**)&wpl, wpl_g);
    cudaGetSymbolAddress((void**)&ch,  ch_g);
    cudaGetSymbolAddress((void**)&cl,  cl_g);

    // 0) splits
    split_kernel<<<(MTOT*DM/4 + 255)/256, 256>>>(x, xh, xl, MTOT*DM/4);
    split_kernel<<<(NQKV*DM/4 + 255)/256, 256>>>(Wqkv, wqh, wql, NQKV*DM/4);
    split_kernel<<<(DM*DM/4 + 255)/256, 256>>>(Wproj, wph, wpl, DM*DM/4);
    // 1) QKV GEMM: q,k fp32 head-major + v bf16 hi/lo
    gemm_bf16<true><<<dim3(NQKV/128, MTOT/128), 256, GEMM_DSMEM>>>(
        xh, xl, wqh, wql, bqkv, nullptr);
    // 2) RoPE -> qh/ql, kh/kl
    rope_kernel<<<(NB*NH*SQ*40)/256, 256>>>(cosp, sinp);
    // 3) attention -> ch/cl
    attn_tc<<<dim3(SQ/128, NB*NH), 256, ATTN_SMEM>>>();
    // 4) output projection
    gemm_bf16<false><<<dim3(DM/128, MTOT/128), 256, GEMM_DSMEM>>>(
        ch, cl, wph, wpl, bproj, out);
}